// round 5
// baseline (speedup 1.0000x reference)
#include <cuda_runtime.h>

#define WIDTH   512
#define HEIGHT  512
#define TH      8                    // output rows per CTA
#define NTH     256                  // threads per CTA
#define ROWB    9328                 // bytes per SMEM row (padded layout, see below)
#define SMEM_BYTES (TH * ROWB)       // 74624

// Layout: tuple for pixel x lives at row byte  64 + 16*x + 16*(x>>3).
// One 16B pad slot every 8 tuples => stage-2 lane stride is 144B, which is
// bank-conflict-free for LDS.128 (banks 4l..4l+3 per 8-lane phase), while
// stage-1 stores (consecutive x) stay contiguous-128B per quarter-warp.
// Reflected x-halos are duplicated at fixed slots:
//   x=-1,-2,-3 (copies of 1,2,3)      at bytes 32,16,0
//   x=512,513,514 (copies 510,509,508) at bytes 9280,9296,9312

typedef unsigned long long u64;

__device__ __forceinline__ int refl(int i, int n) {
    i = i < 0 ? -i : i;
    return i >= n ? 2 * n - 2 - i : i;
}
__device__ __forceinline__ u64 pack2(float lo, float hi) {
    u64 r; asm("mov.b64 %0, {%1, %2};" : "=l"(r) : "f"(lo), "f"(hi)); return r;
}
__device__ __forceinline__ void unpack2(u64 v, float& lo, float& hi) {
    asm("mov.b64 {%0, %1}, %2;" : "=f"(lo), "=f"(hi) : "l"(v));
}
__device__ __forceinline__ u64 fma2(u64 a, u64 b, u64 c) {   // FFMA2
    u64 d; asm("fma.rn.f32x2 %0, %1, %2, %3;" : "=l"(d) : "l"(a), "l"(b), "l"(c));
    return d;
}
__device__ __forceinline__ float frsq_ap(float x) {
    float r; asm("rsqrt.approx.f32 %0, %1;" : "=f"(r) : "f"(x)); return r;
}

__global__ __launch_bounds__(NTH, 3)
void adain_local_kernel(const float* __restrict__ content,
                        const float* __restrict__ style,
                        float* __restrict__ out) {
    extern __shared__ unsigned char sm[];

    const float G[7] = {0.0044330481752437f, 0.0540055826224143f,
                        0.2420362293761143f, 0.3990502746173879f,
                        0.2420362293761143f, 0.0540055826224143f,
                        0.0044330481752437f};
    u64 G2[7];
    #pragma unroll
    for (int k = 0; k < 7; ++k) G2[k] = pack2(G[k], G[k]);

    const int plane = blockIdx.y;
    const int y0    = blockIdx.x * TH;
    const size_t pb = (size_t)plane * (WIDTH * HEIGHT);
    const float* cp = content + pb;
    const float* sp = style   + pb;
    float*       op = out     + pb;
    const int tid = threadIdx.x;

    // -------- Stage 1: vertical 7-tap blur (R2-proven), new store layout ----
    #pragma unroll
    for (int half = 0; half < 2; ++half) {
        const int x = tid + half * NTH;                 // 0..511, coalesced
        const unsigned sbase = (unsigned)(64 + 16 * x + 16 * (x >> 3));
        int hs = -1;                                    // halo duplicate slot
        if (x >= 1 && x <= 3)      hs = 48 - 16 * x;             // 32,16,0
        if (x >= 508 && x <= 510)  hs = 1088 + 16 * (1022 - x);  // 9280/96/9312

        u64 rc[7], rs[7];                               // ring: packed (v, v^2)
        #pragma unroll
        for (int i = 0; i < TH + 6; ++i) {
            const int gy = refl(y0 - 3 + i, HEIGHT);
            const float c = __ldg(cp + gy * WIDTH + x);
            const float s = __ldg(sp + gy * WIDTH + x);
            rc[i % 7] = pack2(c, c * c);
            rs[i % 7] = pack2(s, s * s);
            if (i >= 6) {
                const int o = i - 6;                    // output row in tile
                u64 a = 0ull, d = 0ull;                 // (mean, E2) packed
                #pragma unroll
                for (int k = 0; k < 7; ++k) {
                    const int q = (o + k) % 7;          // compile-time
                    a = fma2(G2[k], rc[q], a);
                    d = fma2(G2[k], rs[q], d);
                }
                ulonglong2 v; v.x = a; v.y = d;
                *reinterpret_cast<ulonglong2*>(sm + o * ROWB + sbase) = v;
                if (hs >= 0)
                    *reinterpret_cast<ulonglong2*>(sm + o * ROWB + hs) = v;
            }
        }
    }
    __syncthreads();

    // ---- Stage 2: horizontal 7-tap + AdaIN; immediate-offset LDS, 2 RSQ ----
    // 512 tasks = TH rows x 64 chunks of 8 px; 2 tasks per thread.
    #pragma unroll
    for (int t = 0; t < 2; ++t) {
        const int task = tid + t * NTH;
        const int row  = task >> 6;               // 0..TH-1
        const int l    = task & 63;               // 8-px chunk id
        const int gy   = y0 + row;
        const int xc   = l << 3;
        const unsigned char* smrow = sm + row * ROWB + 144 * l;

        // hoist raw-content loads (overlap LDG latency with FFMA2 stream)
        const float4 cA = *reinterpret_cast<const float4*>(cp + gy * WIDTH + xc);
        const float4 cB = *reinterpret_cast<const float4*>(cp + gy * WIDTH + xc + 4);

        u64 ac[8], as_[8];
        #pragma unroll
        for (int o = 0; o < 8; ++o) { ac[o] = 0ull; as_[o] = 0ull; }

        #pragma unroll
        for (int j = 0; j < 14; ++j) {
            // window x = 8l + j - 3; byte = 144l + 16j + {0,16,32} (immediate)
            const int Cj = 16 * j + ((j < 3) ? 0 : (j < 11) ? 16 : 32);
            const ulonglong2 w =
                *reinterpret_cast<const ulonglong2*>(smrow + Cj);
            #pragma unroll
            for (int o = 0; o < 8; ++o) {
                const int k = j - o;
                if (k >= 0 && k < 7) {                // compile-time predicate
                    ac[o]  = fma2(G2[k], w.x, ac[o]);
                    as_[o] = fma2(G2[k], w.y, as_[o]);
                }
            }
        }

        const float craw[8] = {cA.x, cA.y, cA.z, cA.w, cB.x, cB.y, cB.z, cB.w};

        float res[8];
        #pragma unroll
        for (int o = 0; o < 8; ++o) {
            float cm, cE2, smn, sE2;
            unpack2(ac[o],  cm,  cE2);
            unpack2(as_[o], smn, sE2);
            const float cv = fmaxf(fmaf(-cm,  cm,  cE2), 1e-6f);
            const float sv = fmaxf(fmaf(-smn, smn, sE2), 1e-6f);
            const float rqc = frsq_ap(cv);            // MUFU.RSQ
            const float rqs = frsq_ap(sv);            // MUFU.RSQ
            const float numer = fmaf(sv, rqs, 1e-5f); // sqrt(sv)+eps
            const float u  = 1e-5f * rqc;             // eps*rsq(cv), <=1e-2
            const float w2 = fmaf(u, u, 1.0f) - u;    // 1 - u + u^2
            const float dinv = rqc * w2;              // ~ 1/(sqrt(cv)+eps)
            res[o] = fmaf(craw[o] - cm, numer * dinv, smn);
        }

        *reinterpret_cast<float4*>(op + gy * WIDTH + xc) =
            make_float4(res[0], res[1], res[2], res[3]);
        *reinterpret_cast<float4*>(op + gy * WIDTH + xc + 4) =
            make_float4(res[4], res[5], res[6], res[7]);
    }
}

extern "C" void kernel_launch(void* const* d_in, const int* in_sizes, int n_in,
                              void* d_out, int out_size) {
    const float* content = (const float*)d_in[0];
    const float* style   = (const float*)d_in[1];
    float*       out     = (float*)d_out;

    const int planes = in_sizes[0] / (WIDTH * HEIGHT);   // 4*64 = 256

    cudaFuncSetAttribute(adain_local_kernel,
                         cudaFuncAttributeMaxDynamicSharedMemorySize, SMEM_BYTES);

    dim3 grid(HEIGHT / TH, planes);
    adain_local_kernel<<<grid, NTH, SMEM_BYTES>>>(content, style, out);
}

// round 6
// speedup vs baseline: 1.2937x; 1.2937x over previous
#include <cuda_runtime.h>

#define WIDTH   512
#define HEIGHT  512
#define TH      8                  // output rows per CTA
#define NTH     256                // threads per CTA
#define ROWB    (WIDTH * 16)       // bytes per SMEM vb row (512 x 16B tuples)
#define SMEM_BYTES (TH * ROWB)     // 65536

typedef unsigned long long u64;

// reflect padding (pad=3 < dim, single reflection suffices)
__device__ __forceinline__ int refl(int i, int n) {
    i = i < 0 ? -i : i;
    return i >= n ? 2 * n - 2 - i : i;
}

// XOR swizzle: byte offset of tuple #x within a vb row.
// x' = x ^ ((x>>3)&7): stride-8 accesses (stage-2 lanes) land on distinct
// 16B slots -> conflict-free LDS.128 / STS.128.
__device__ __forceinline__ unsigned vboff(int x) {
    return (unsigned)((x ^ ((x >> 3) & 7)) << 4);
}

__device__ __forceinline__ u64 pack2(float lo, float hi) {
    u64 r; asm("mov.b64 %0, {%1, %2};" : "=l"(r) : "f"(lo), "f"(hi)); return r;
}
__device__ __forceinline__ void unpack2(u64 v, float& lo, float& hi) {
    asm("mov.b64 {%0, %1}, %2;" : "=f"(lo), "=f"(hi) : "l"(v));
}
// packed dual FMA -> FFMA2 in SASS (PTX-only form)
__device__ __forceinline__ u64 fma2(u64 a, u64 b, u64 c) {
    u64 d; asm("fma.rn.f32x2 %0, %1, %2, %3;" : "=l"(d) : "l"(a), "l"(b), "l"(c));
    return d;
}
__device__ __forceinline__ float frsq_ap(float x) {
    float r; asm("rsqrt.approx.f32 %0, %1;" : "=f"(r) : "f"(x)); return r;
}

__global__ __launch_bounds__(NTH, 3)
void adain_local_kernel(const float* __restrict__ content,
                        const float* __restrict__ style,
                        float* __restrict__ out) {
    extern __shared__ unsigned char sm[];

    // Gaussian taps (sigma=1, k=7), normalized; packed into both f32x2 lanes.
    const float G[7] = {0.0044330481752437f, 0.0540055826224143f,
                        0.2420362293761143f, 0.3990502746173879f,
                        0.2420362293761143f, 0.0540055826224143f,
                        0.0044330481752437f};
    u64 G2[7];
    #pragma unroll
    for (int k = 0; k < 7; ++k) G2[k] = pack2(G[k], G[k]);

    const int plane = blockIdx.y;
    const int y0    = blockIdx.x * TH;
    const size_t pb = (size_t)plane * (WIDTH * HEIGHT);
    const float* cp = content + pb;
    const float* sp = style   + pb;
    float*       op = out     + pb;
    const int tid = threadIdx.x;

    // -------- Stage 1: vertical 7-tap blur; each thread handles 2 columns ---
    #pragma unroll
    for (int half = 0; half < 2; ++half) {
        const int x = tid + half * NTH;        // 0..511, coalesced per row
        u64 rc[7], rs[7];                      // ring: packed (v, v^2)
        #pragma unroll
        for (int i = 0; i < TH + 6; ++i) {
            const int gy = refl(y0 - 3 + i, HEIGHT);
            const float c = __ldg(cp + gy * WIDTH + x);
            const float s = __ldg(sp + gy * WIDTH + x);
            rc[i % 7] = pack2(c, c * c);
            rs[i % 7] = pack2(s, s * s);
            if (i >= 6) {
                const int o = i - 6;           // output row within tile
                u64 a = 0ull, d = 0ull;        // (c_mean, c_E2), (s_mean, s_E2)
                #pragma unroll
                for (int k = 0; k < 7; ++k) {
                    const int q = (o + k) % 7; // compile-time after unroll
                    a = fma2(G2[k], rc[q], a);
                    d = fma2(G2[k], rs[q], d);
                }
                ulonglong2 v; v.x = a; v.y = d;
                *reinterpret_cast<ulonglong2*>(sm + o * ROWB + vboff(x)) = v;
            }
        }
    }
    __syncthreads();

    // ---- Stage 2: horizontal 7-tap + AdaIN epilogue; accumulate-on-load ----
    // 512 tasks = TH rows x 64 chunks of 8 pixels; 2 tasks per thread.
    #pragma unroll
    for (int t = 0; t < 2; ++t) {
        const int task = tid + t * NTH;
        const int row  = task >> 6;            // 0..TH-1
        const int xc   = (task & 63) << 3;     // chunk start column, 8-aligned
        const int gy   = y0 + row;
        const unsigned char* smrow = sm + row * ROWB;

        // hoist raw-content loads (overlap their latency with the FFMA2 stream)
        const float4 cA = *reinterpret_cast<const float4*>(cp + gy * WIDTH + xc);
        const float4 cB = *reinterpret_cast<const float4*>(cp + gy * WIDTH + xc + 4);

        u64 ac[8], as_[8];                     // packed accumulators per pixel
        #pragma unroll
        for (int o = 0; o < 8; ++o) { ac[o] = 0ull; as_[o] = 0ull; }

        #pragma unroll
        for (int j = 0; j < 14; ++j) {
            const int xi = refl(xc - 3 + j, WIDTH);
            const ulonglong2 w =
                *reinterpret_cast<const ulonglong2*>(smrow + vboff(xi));
            #pragma unroll
            for (int o = 0; o < 8; ++o) {
                const int k = j - o;
                if (k >= 0 && k < 7) {         // compile-time predicate
                    ac[o]  = fma2(G2[k], w.x, ac[o]);
                    as_[o] = fma2(G2[k], w.y, as_[o]);
                }
            }
        }

        const float craw[8] = {cA.x, cA.y, cA.z, cA.w, cB.x, cB.y, cB.z, cB.w};

        float res[8];
        #pragma unroll
        for (int o = 0; o < 8; ++o) {
            float cm, cE2, smn, sE2;
            unpack2(ac[o],  cm,  cE2);
            unpack2(as_[o], smn, sE2);
            const float cv = fmaxf(fmaf(-cm,  cm,  cE2), 1e-6f);
            const float sv = fmaxf(fmaf(-smn, smn, sE2), 1e-6f);
            const float rqc = frsq_ap(cv);              // MUFU.RSQ (parallel)
            const float rqs = frsq_ap(sv);              // MUFU.RSQ (parallel)
            const float numer = fmaf(sv, rqs, 1e-5f);   // sqrt(sv) + eps
            const float dinv  = rqc - (1e-5f * rqc) * rqc; // ~1/(sqrt(cv)+eps)
            res[o] = fmaf(craw[o] - cm, numer * dinv, smn);
        }

        *reinterpret_cast<float4*>(op + gy * WIDTH + xc) =
            make_float4(res[0], res[1], res[2], res[3]);
        *reinterpret_cast<float4*>(op + gy * WIDTH + xc + 4) =
            make_float4(res[4], res[5], res[6], res[7]);
    }
}

extern "C" void kernel_launch(void* const* d_in, const int* in_sizes, int n_in,
                              void* d_out, int out_size) {
    const float* content = (const float*)d_in[0];
    const float* style   = (const float*)d_in[1];
    float*       out     = (float*)d_out;

    const int planes = in_sizes[0] / (WIDTH * HEIGHT);   // 4*64 = 256

    cudaFuncSetAttribute(adain_local_kernel,
                         cudaFuncAttributeMaxDynamicSharedMemorySize, SMEM_BYTES);

    dim3 grid(HEIGHT / TH, planes);
    adain_local_kernel<<<grid, NTH, SMEM_BYTES>>>(content, style, out);
}